// round 15
// baseline (speedup 1.0000x reference)
#include <cuda_runtime.h>
#include <cuda_bf16.h>
#include <cstdint>

// ---------------------------------------------------------------------------
// SpatialNonIntersectionAxiom — overlapped capture graph:
//   branch A (s2): driver memset of mask+score planes (DRAM-bound ~21us)
//   branch B     : memset(bk) -> prep -> compute(record violations)
//   join         : scatter violations + write out[0]
// out[0]=loss, out[1..1+E^2)=violation_mask, out[1+E^2..1+2E^2)=scores (f32).
// Integer fixed-point (2^-40) totals + value-pure scatter to distinct cells
// -> bit-deterministic outputs across graph replays.
// Rules learned: NO warp collectives inside non-uniform loops (R12 hang);
// NO hand-rolled fill co-resident with compute (R13 10x); driver memset only.
// ---------------------------------------------------------------------------

#define MAXE  8192
#define MAXB  16
#define BLK   256
#define CHNK  96
#define SMAXL 768
#define VCAP  (1 * 1024 * 1024)

// Batch-major per-edge tables (__device__: no allocs allowed)
__device__ float4 g_tP[MAXB * MAXE]; // psx, psy, d1x, d1y
__device__ float4 g_tM[MAXB * MAXE]; // midx, midy, hh=half+0.075, packed(s<<12|d)
__device__ float4 g_tD[MAXB * MAXE]; // dda, sq(clamped), rinv=1/sq, edgeIdx bits
__device__ uint2  g_viol[VCAP];      // x = (i<<12)|j, y = pl bits

struct Bookkeep {
    unsigned long long totQ;   // fixed-point 2^-40 loss sum
    unsigned long long totC;   // candidate count (n_pairs)
    unsigned int nViol;        // violation list length
    unsigned int pad;
    int bcnt[MAXB];            // per-batch table lengths
};
__device__ Bookkeep g_bk;

__global__ void prep_kernel(const float* __restrict__ pos,
                            const int* __restrict__ ei,
                            int E, int N, int nodes) {
    int e = blockIdx.x * blockDim.x + threadIdx.x;
    if (e >= E) return;
    int s = ei[e];
    int d = ei[E + e];
    s = min(max(s, 0), nodes - 1);
    d = min(max(d, 0), nodes - 1);
    float psx = pos[2 * s],  psy = pos[2 * s + 1];
    float pdx = pos[2 * d],  pdy = pos[2 * d + 1];
    float d1x = pdx - psx,   d1y = pdy - psy;
    float rawsq = d1x * d1x + d1y * d1y;
    float sq    = fmaxf(rawsq, 1e-12f);
    float rinv  = __fdiv_rn(1.0f, sq);
    float half  = __fsqrt_rn(rawsq) * 0.5f;
    float midx  = (psx + pdx) * 0.5f;
    float midy  = (psy + pdy) * 0.5f;
    float dda   = d1x * psx + d1y * psy;
    int b = min(s / N, MAXB - 1);
    unsigned int packed = (((unsigned int)s & 0xFFFu) << 12)
                        | ((unsigned int)d & 0xFFFu);

    // Warp-aggregated append (single non-divergent region; E multiple of
    // blockDim in practice — activemask covers stragglers correctly).
    unsigned int am  = __activemask();
    unsigned int grp = __match_any_sync(am, b);
    int leader = __ffs(grp) - 1;
    int myrank = __popc(grp & ((1u << (threadIdx.x & 31)) - 1u));
    int p0 = 0;
    if ((threadIdx.x & 31) == leader)
        p0 = atomicAdd(&g_bk.bcnt[b], __popc(grp));
    p0 = __shfl_sync(am, p0, leader);
    int p = p0 + myrank;

    if (p < MAXE) {
        int o = b * MAXE + p;
        g_tP[o] = make_float4(psx, psy, d1x, d1y);
        g_tM[o] = make_float4(midx, midy, half + 0.075f,
                              __uint_as_float(packed));
        g_tD[o] = make_float4(dda, sq, rinv, __int_as_float(e));
    }
}

// grid = (CHNK, B). SMEM-staged, branchless pair math (R10, 18.3us proven);
// violations appended with plain per-thread atomics (no warp collectives).
__global__ void __launch_bounds__(BLK)
compute_kernel(int E) {
    __shared__ float4 sP[SMAXL];
    __shared__ float4 sM[SMAXL];
    __shared__ float4 sD[SMAXL];

    const int b = blockIdx.y;
    const int c = blockIdx.x;
    const int L = min(g_bk.bcnt[b], MAXE);
    const bool inSmem = (L <= SMAXL);
    const int lane = threadIdx.x & 31;

    const float4* __restrict__ P = inSmem ? sP : (g_tP + b * MAXE);
    const float4* __restrict__ M = inSmem ? sM : (g_tM + b * MAXE);
    const float4* __restrict__ D = inSmem ? sD : (g_tD + b * MAXE);

    if (inSmem) {
        for (int k = threadIdx.x; k < L; k += BLK) {
            int o = b * MAXE + k;
            sP[k] = g_tP[o]; sM[k] = g_tM[o]; sD[k] = g_tD[o];
        }
        __syncthreads();
    }

    unsigned long long accQ = 0ull;
    unsigned int       cnt  = 0u;

    for (int ki = c; ki < L; ki += CHNK) {
        float4 rP = P[ki], rM = M[ki], rD = D[ki];
        unsigned int pr = __float_as_uint(rM.w);
        unsigned int rs = pr >> 12, rd = pr & 0xFFFu;
        int re = __float_as_int(rD.w);

        for (int kj = ki + 1 + threadIdx.x; kj < L; kj += BLK) {
            float4 qM = M[kj];
            float4 qP = P[kj];
            float4 qD = D[kj];
            unsigned int pq = __float_as_uint(qM.w);
            unsigned int qs = pq >> 12, qd = pq & 0xFFFu;
            bool shares = (rs == qs) | (rs == qd) | (rd == qs) | (rd == qd);
            float dx = rM.x - qM.x;
            float dy = rM.y - qM.y;
            float d2 = dx * dx + dy * dy;
            float reach = rM.z + qM.z;            // half_i+half_j+0.15
            bool maskok = (!shares) && (d2 < reach * reach);
            cnt += maskok ? 1u : 0u;

            // Branchless segment distance (orient i = smaller edge index)
            int qe = __float_as_int(qD.w);
            bool sw = re > qe;
            float iAx = sw ? qP.x : rP.x, iAy = sw ? qP.y : rP.y;
            float iAz = sw ? qP.z : rP.z, iAw = sw ? qP.w : rP.w;
            float jAx = sw ? rP.x : qP.x, jAy = sw ? rP.y : qP.y;
            float jAz = sw ? rP.z : qP.z, jAw = sw ? rP.w : qP.w;
            float iDd = sw ? qD.x : rD.x, jDd = sw ? rD.x : qD.x;
            float A   = sw ? qD.y : rD.y, Ee  = sw ? rD.y : qD.y;
            float rA  = sw ? qD.z : rD.z, rE  = sw ? rD.z : qD.z;

            float bb = iAz * jAz + iAw * jAw;
            float cc = iDd - (iAz * jAx + iAw * jAy);
            float ff = (iAx * jAz + iAy * jAw) - jDd;
            float denom = fmaxf(A * Ee - bb * bb, 1e-12f);
            float s = (bb * ff - cc * Ee) * __frcp_rn(denom);
            s = fminf(fmaxf(s, 0.0f), 1.0f);
            float t = fminf(fmaxf((bb * s + ff) * rE, 0.0f), 1.0f);
            s = fminf(fmaxf((bb * t - cc) * rA, 0.0f), 1.0f);
            float cax = iAx + s * iAz;
            float cay = iAy + s * iAw;
            float cbx = jAx + t * jAz;
            float cby = jAy + t * jAw;
            float ddx = cax - cbx, ddy = cay - cby;
            float dmsq = ddx * ddx + ddy * ddy;

            if (maskok && dmsq < 1.01e-6f) {      // rare: real violations
                float dmin = __fsqrt_rn(dmsq);
                float pl = 0.001f - dmin;
                if (pl > 0.0f) {
                    accQ += (unsigned long long)
                        __double2ll_rn((double)pl * 1099511627776.0);
                    unsigned int pos = atomicAdd(&g_bk.nViol, 1u);
                    if (pos < VCAP) {
                        int i = sw ? qe : re, j = sw ? re : qe;
                        g_viol[pos] = make_uint2(
                            ((unsigned int)i << 12) | (unsigned int)j,
                            __float_as_uint(pl));
                    }
                }
            }
        }
    }

    // Uniform reduction -> global integer totals
#pragma unroll
    for (int o = 16; o; o >>= 1) {
        accQ += __shfl_xor_sync(0xffffffffu, accQ, o);
        cnt  += __shfl_xor_sync(0xffffffffu, cnt,  o);
    }
    __shared__ unsigned long long rQ[BLK / 32];
    __shared__ unsigned int       rC[BLK / 32];
    int w = threadIdx.x >> 5;
    if (lane == 0) { rQ[w] = accQ; rC[w] = cnt; }
    __syncthreads();
    if (threadIdx.x == 0) {
        unsigned long long q = 0ull; unsigned int cc2 = 0u;
#pragma unroll
        for (int k = 0; k < BLK / 32; k++) { q += rQ[k]; cc2 += rC[k]; }
        if (q) atomicAdd(&g_bk.totQ, q);
        if (cc2) atomicAdd(&g_bk.totC, (unsigned long long)cc2);
    }
}

// Join kernel: scatter recorded violations over the zeroed planes + loss.
__global__ void scatter_kernel(float* __restrict__ out, int E, int writeBig) {
    if (blockIdx.x == 0 && threadIdx.x == 0) {
        double sum = (double)g_bk.totQ * (1.0 / 1099511627776.0);
        unsigned long long n = g_bk.totC ? g_bk.totC : 1ull;
        out[0] = (float)(sum / (double)n);
    }
    if (!writeBig) return;
    float* __restrict__ outM = out + 1;
    float* __restrict__ outS = out + 1 + (size_t)E * (size_t)E;
    unsigned int nv = min(g_bk.nViol, (unsigned int)VCAP);
    for (unsigned int k = blockIdx.x * blockDim.x + threadIdx.x; k < nv;
         k += gridDim.x * blockDim.x) {
        uint2 v = g_viol[k];
        int i = (int)(v.x >> 12);
        int j = (int)(v.x & 0xFFFu);
        size_t off = (size_t)i * (size_t)E + (size_t)j;
        outM[off] = 1.0f;
        outS[off] = __uint_as_float(v.y);
    }
}

extern "C" void kernel_launch(void* const* d_in, const int* in_sizes, int n_in,
                              void* d_out, int out_size) {
    const float* pos = (const float*)d_in[0];
    // d_in[1] = adjacency: unused by the reference computation
    const int*   ei  = (const int*)d_in[2];

    int E     = in_sizes[2] / 2;
    int nodes = in_sizes[0] / 2;
    int N     = in_sizes[1] / nodes;
    int B     = min((nodes + N - 1) / N, MAXB);

    long long need = 1ll + 2ll * (long long)E * (long long)E;
    int writeBig = ((long long)out_size >= need) ? 1 : 0;

    float* out = (float*)d_out;

    // Lazy host-side stream/events (host objects, not device memory)
    static cudaStream_t s2 = nullptr;
    static cudaEvent_t evFork = nullptr, evJoin = nullptr;
    if (!s2) {
        cudaStreamCreateWithFlags(&s2, cudaStreamNonBlocking);
        cudaEventCreateWithFlags(&evFork, cudaEventDisableTiming);
        cudaEventCreateWithFlags(&evJoin, cudaEventDisableTiming);
    }

    void* bkPtr = nullptr;
    cudaGetSymbolAddress(&bkPtr, g_bk);

    // ---- Fork: branch A = driver memset of planes on s2 ----
    cudaEventRecord(evFork, 0);
    cudaStreamWaitEvent(s2, evFork, 0);
    if (writeBig) {
        cudaMemsetAsync(out + 1, 0,
                        2ull * (size_t)E * (size_t)E * sizeof(float), s2);
    } else if (out_size > 1) {
        cudaMemsetAsync(out + 1, 0, ((size_t)out_size - 1) * sizeof(float), s2);
    }
    cudaEventRecord(evJoin, s2);

    // ---- Branch B on capture stream: bk clear -> prep -> compute ----
    cudaMemsetAsync(bkPtr, 0, sizeof(Bookkeep));
    prep_kernel<<<(E + 127) / 128, 128>>>(pos, ei, E, N, nodes);
    dim3 grid(CHNK, B);
    compute_kernel<<<grid, BLK>>>(E);

    // ---- Join: scatter + loss after both branches ----
    cudaStreamWaitEvent(0, evJoin, 0);
    scatter_kernel<<<64, BLK>>>(out, E, writeBig);
}